// round 3
// baseline (speedup 1.0000x reference)
#include <cuda_runtime.h>

// Problem: B=1, H=16, S=4096, D=64, fp32, NO softmax.
// (Q K^T) V == Q (K^T V);  K^T V is [64x64] per head -> 64x fewer FLOPs.
// This round: packed f32x2 FFMA (2 lanes per fma-pipe slot) in both GEMMs.
#define HEADS 16
#define SEQ   4096
#define DIM   64
#define NSPLIT 32
#define CHUNK (SEQ / NSPLIT)   // 128 rows per partial block

__device__ __align__(16) float g_partial[HEADS * NSPLIT * DIM * DIM];  // 8 MB
__device__ __align__(16) float g_M[HEADS * DIM * DIM];                 // 256 KB

// ---- f32x2 packed helpers -------------------------------------------------
__device__ __forceinline__ void ffma2(unsigned long long& acc,
                                      unsigned long long a,
                                      unsigned long long b) {
    asm("fma.rn.f32x2 %0, %1, %2, %0;" : "+l"(acc) : "l"(a), "l"(b));
}
__device__ __forceinline__ unsigned long long bcast2(float x) {
    unsigned long long r;
    asm("mov.b64 %0, {%1, %1};" : "=l"(r) : "f"(x));
    return r;
}

// ---------------------------------------------------------------------------
// Kernel 1: partial M = K_chunk^T @ V_chunk.
// 128 threads; thread (ci,cj) owns a 4x8 tile: rows ci*4.., cols cj*8..
// ---------------------------------------------------------------------------
__global__ __launch_bounds__(128) void ktv_partial(const float* __restrict__ Kp,
                                                   const float* __restrict__ Vp) {
    const int h  = blockIdx.x / NSPLIT;
    const int sp = blockIdx.x % NSPLIT;
    const float* Kh = Kp + ((size_t)h * SEQ + (size_t)sp * CHUNK) * DIM;
    const float* Vh = Vp + ((size_t)h * SEQ + (size_t)sp * CHUNK) * DIM;

    __shared__ __align__(16) float Ks[32][DIM];
    __shared__ __align__(16) float Vs[32][DIM];

    const int tid = threadIdx.x;
    const int ci = tid >> 3;   // 0..15 -> K-dim rows 4*ci..
    const int cj = tid & 7;    // 0..7  -> V-dim cols 8*cj..

    unsigned long long acc[4][4] = {};   // 4 rows x 4 f32x2 (8 cols)

    for (int t = 0; t < CHUNK; t += 32) {
        // cooperative load: 32 rows x 64 floats each of K,V (512 float4 each)
        #pragma unroll
        for (int i = tid; i < 32 * 16; i += 128) {
            const int r  = i >> 4;
            const int c4 = (i & 15) << 2;
            *(float4*)&Ks[r][c4] = *(const float4*)&Kh[(size_t)(t + r) * DIM + c4];
            *(float4*)&Vs[r][c4] = *(const float4*)&Vh[(size_t)(t + r) * DIM + c4];
        }
        __syncthreads();

        #pragma unroll
        for (int s = 0; s < 32; s++) {
            const float4 kv = *(const float4*)&Ks[s][ci * 4];
            const ulonglong2 v01 = *(const ulonglong2*)&Vs[s][cj * 8];
            const ulonglong2 v23 = *(const ulonglong2*)&Vs[s][cj * 8 + 4];
            const unsigned long long vb[4] = {v01.x, v01.y, v23.x, v23.y};
            const unsigned long long ka[4] = {bcast2(kv.x), bcast2(kv.y),
                                              bcast2(kv.z), bcast2(kv.w)};
            #pragma unroll
            for (int a = 0; a < 4; a++)
                #pragma unroll
                for (int b = 0; b < 4; b++)
                    ffma2(acc[a][b], ka[a], vb[b]);
        }
        __syncthreads();
    }

    float* outp = g_partial + ((size_t)h * NSPLIT + sp) * DIM * DIM;
    #pragma unroll
    for (int a = 0; a < 4; a++) {
        const int row = ci * 4 + a;
        *(ulonglong2*)&outp[row * DIM + cj * 8]     = make_ulonglong2(acc[a][0], acc[a][1]);
        *(ulonglong2*)&outp[row * DIM + cj * 8 + 4] = make_ulonglong2(acc[a][2], acc[a][3]);
    }
}

// ---------------------------------------------------------------------------
// Kernel 2: reduce NSPLIT partials -> g_M (float4-vectorized).
// HEADS*DIM*DIM/4 = 16384 float4 sums.
// ---------------------------------------------------------------------------
__global__ __launch_bounds__(256) void reduce_m() {
    const int idx = blockIdx.x * 256 + threadIdx.x;   // float4 index
    if (idx >= HEADS * DIM * DIM / 4) return;
    const int h = idx / (DIM * DIM / 4);
    const int e = idx % (DIM * DIM / 4);
    float4 s = make_float4(0.f, 0.f, 0.f, 0.f);
    #pragma unroll
    for (int p = 0; p < NSPLIT; p++) {
        const float4 t = *(const float4*)&g_partial[(((size_t)h * NSPLIT + p) * DIM * DIM) + e * 4];
        s.x += t.x; s.y += t.y; s.z += t.z; s.w += t.w;
    }
    *(float4*)&g_M[(size_t)idx * 4] = s;
}

// ---------------------------------------------------------------------------
// Kernel 3: out = Q @ M.  64 q-rows x 64 cols per block, 128 threads,
// thread (ci,cj) owns 4 q-rows x 8 cols; Q tile transposed in smem.
// ---------------------------------------------------------------------------
#define QROWS 64
__global__ __launch_bounds__(128) void qm_gemm(const float* __restrict__ Qp,
                                               float* __restrict__ Op) {
    const int blocksPerHead = SEQ / QROWS;                 // 64
    const int h  = blockIdx.x / blocksPerHead;
    const int r0 = (blockIdx.x % blocksPerHead) * QROWS;

    __shared__ __align__(16) float Qt[DIM][QROWS + 4];   // Qt[k][row], +4 pad keeps 16B align
    __shared__ __align__(16) float Ms[DIM][DIM];

    const int tid = threadIdx.x;
    const float* Qh = Qp + ((size_t)h * SEQ + r0) * DIM;
    const float* Mh = g_M + (size_t)h * DIM * DIM;

    // load M (1024 float4, 8 per thread)
    #pragma unroll
    for (int i = tid; i < DIM * DIM / 4; i += 128) {
        const int r  = i >> 4;
        const int c4 = (i & 15) << 2;
        *(float4*)&Ms[r][c4] = *(const float4*)&Mh[r * DIM + c4];
    }
    // load Q tile, transpose into smem
    #pragma unroll
    for (int i = tid; i < QROWS * DIM / 4; i += 128) {
        const int r  = i >> 4;          // q-row 0..63
        const int c4 = (i & 15) << 2;   // k 0..60
        const float4 qv = *(const float4*)&Qh[(size_t)r * DIM + c4];
        Qt[c4 + 0][r] = qv.x;
        Qt[c4 + 1][r] = qv.y;
        Qt[c4 + 2][r] = qv.z;
        Qt[c4 + 3][r] = qv.w;
    }
    __syncthreads();

    const int ci = tid >> 3;   // 0..15 -> q rows 4*ci..
    const int cj = tid & 7;    // 0..7  -> out cols 8*cj..

    unsigned long long acc[4][4] = {};
    #pragma unroll
    for (int k = 0; k < DIM; k++) {
        const float4 qv = *(const float4*)&Qt[k][ci * 4];          // (68k+4ci)*4 % 16 == 0
        const ulonglong2 m01 = *(const ulonglong2*)&Ms[k][cj * 8];
        const ulonglong2 m23 = *(const ulonglong2*)&Ms[k][cj * 8 + 4];
        const unsigned long long mb[4] = {m01.x, m01.y, m23.x, m23.y};
        const unsigned long long qa[4] = {bcast2(qv.x), bcast2(qv.y),
                                          bcast2(qv.z), bcast2(qv.w)};
        #pragma unroll
        for (int a = 0; a < 4; a++)
            #pragma unroll
            for (int b = 0; b < 4; b++)
                ffma2(acc[a][b], qa[a], mb[b]);
    }

    float* Oh = Op + ((size_t)h * SEQ + r0) * DIM;
    #pragma unroll
    for (int a = 0; a < 4; a++) {
        const int row = ci * 4 + a;
        *(ulonglong2*)&Oh[(size_t)row * DIM + cj * 8]     = make_ulonglong2(acc[a][0], acc[a][1]);
        *(ulonglong2*)&Oh[(size_t)row * DIM + cj * 8 + 4] = make_ulonglong2(acc[a][2], acc[a][3]);
    }
}

// ---------------------------------------------------------------------------
extern "C" void kernel_launch(void* const* d_in, const int* in_sizes, int n_in,
                              void* d_out, int out_size) {
    const float* q = (const float*)d_in[0];
    const float* k = (const float*)d_in[1];
    const float* v = (const float*)d_in[2];
    float* out = (float*)d_out;

    ktv_partial<<<HEADS * NSPLIT, 128>>>(k, v);
    reduce_m<<<(HEADS * DIM * DIM / 4 + 255) / 256, 256>>>();
    qm_gemm<<<HEADS * (SEQ / QROWS), 128>>>(q, out);
}